// round 9
// baseline (speedup 1.0000x reference)
#include <cuda_runtime.h>
#include <cstdint>

// Problem constants (fixed by the dataset)
#define B 8
#define N 2048
#define IN_F 512
#define OUT_F 128
#define TR 16

// Scratch (allocation-free rule: __device__ globals), 16B-aligned for float4
__device__ __align__(16) float g_w1[IN_F];
__device__ __align__(16) float g_w2[IN_F];
__device__ __align__(16) float g_x8[B * N];   // 0.125 * (emb1[b,i,:] . w1)
__device__ __align__(16) float g_y8[B * N];   // 0.125 * (emb1[b,i,:] . w2)
__device__ __align__(16) float g_xm[B * N];   // act ? x8 : -1e30
__device__ __align__(16) float g_ym[B * N];   // act ? y8 : -1e30
__device__ float g_scale[B];

// Sense-reversing grid barrier state (self-resetting; generation counter is
// monotone across graph replays, comparisons are by inequality only)
__device__ unsigned g_count;
__device__ volatile unsigned g_gen;

__device__ __forceinline__ float tanh_fast(float x) {
    float r;
    asm("tanh.approx.f32 %0, %1;" : "=f"(r) : "f"(x));
    return r;
}

// Software grid barrier. SAFE ONLY because grid == exactly one co-resident
// wave (grid sized via cudaOccupancyMaxActiveBlocksPerMultiprocessor).
__device__ __forceinline__ void grid_barrier() {
    __syncthreads();
    if (threadIdx.x == 0) {
        __threadfence();                         // release: my stores -> L2
        unsigned gen = g_gen;
        if (atomicAdd(&g_count, 1u) == gridDim.x - 1) {
            g_count = 0;
            __threadfence();                     // count reset before gen flip
            g_gen = gen + 1;
        } else {
            while (g_gen == gen) __nanosleep(32);
        }
        __threadfence();                         // acquire
    }
    __syncthreads();
}

__global__ void __launch_bounds__(256, 6)
k_persist(const float* __restrict__ emb,
          const float* __restrict__ W,
          const float* __restrict__ a1,
          const float* __restrict__ a2,
          const int*   __restrict__ n_src,
          const int*   __restrict__ ns_tgt,
          float* __restrict__ out) {
    __shared__ __align__(16) unsigned char s_pool[8320];
    const int G    = gridDim.x;
    const int bid  = blockIdx.x;
    const int tid  = threadIdx.x;
    const int lane = tid & 31;

    // ─── Phase W: w1 = W^T a1, w2 = W^T a2 (blocks 0..15) ────────────────
    if (bid < 16) {
        int oq = tid >> 5;                       // 0..7
        int f  = bid * 32 + lane;                // 0..511
        float s1 = 0.f, s2 = 0.f;
#pragma unroll
        for (int o = oq * 16; o < oq * 16 + 16; o++) {
            float w = __ldg(W + (size_t)o * IN_F + f);
            s1 = fmaf(w, __ldg(a1 + o), s1);
            s2 = fmaf(w, __ldg(a2 + o), s2);
        }
        float* p1 = (float*)s_pool;              // [256]
        float* p2 = p1 + 256;                    // [256]
        p1[tid] = s1;
        p2[tid] = s2;
        __syncthreads();
        if (tid < 32) {
            float r1 = 0.f, r2 = 0.f;
#pragma unroll
            for (int c = 0; c < 8; c++) {
                r1 += p1[lane + 32 * c];
                r2 += p2[lane + 32 * c];
            }
            g_w1[f] = r1;
            g_w2[f] = r2;
        }
    }
    grid_barrier();

    // ─── Phase XY: x = emb.w1, y = emb.w2 (pre-scaled by 0.125) ──────────
    {
        float4* sW = (float4*)s_pool;            // [256]: w1 0..127, w2 128..255
        if (tid < 128) sW[tid] = reinterpret_cast<const float4*>(g_w1)[tid];
        else           sW[tid] = reinterpret_cast<const float4*>(g_w2)[tid - 128];
        __syncthreads();

        int warp      = tid >> 5;                // 0..7
        int gwarp     = bid * 8 + warp;
        int totWarps  = G * 8;
        // 8192 warp-tasks, 2 rows each
        for (int task = gwarp; task < (B * N) / 2; task += totWarps) {
            int row0 = task * 2;
            float s1[2] = {0.f, 0.f}, s2[2] = {0.f, 0.f};
#pragma unroll
            for (int r = 0; r < 2; r++) {
                const float4* row = reinterpret_cast<const float4*>(emb + (size_t)(row0 + r) * IN_F);
#pragma unroll
                for (int k = 0; k < 4; k++) {
                    int idx = lane + 32 * k;
                    float4 e  = row[idx];
                    float4 v1 = sW[idx];
                    float4 v2 = sW[128 + idx];
                    s1[r] = fmaf(e.x, v1.x, fmaf(e.y, v1.y, fmaf(e.z, v1.z, fmaf(e.w, v1.w, s1[r]))));
                    s2[r] = fmaf(e.x, v2.x, fmaf(e.y, v2.y, fmaf(e.z, v2.z, fmaf(e.w, v2.w, s2[r]))));
                }
            }
#pragma unroll
            for (int off = 16; off; off >>= 1) {
#pragma unroll
                for (int r = 0; r < 2; r++) {
                    s1[r] += __shfl_down_sync(0xffffffffu, s1[r], off);
                    s2[r] += __shfl_down_sync(0xffffffffu, s2[r], off);
                }
            }
            if (lane == 0) {
#pragma unroll
                for (int r = 0; r < 2; r++) {
                    g_x8[row0 + r] = s1[r] * 0.125f;
                    g_y8[row0 + r] = s2[r] * 0.125f;
                }
            }
        }
    }
    grid_barrier();

    // ─── Phase SEL: stable descending rank of y; sentinel arrays ─────────
    // 512 tasks: b = t>>6, 32 columns per task, 8 threads per column.
    for (int t = bid; t < 512; t += G) {
        int b    = t >> 6;
        int blk  = t & 63;
        int jb   = blk * 32;
        int ns   = ns_tgt[b];
        int nsrc = n_src[b];
        int kb   = (int)((float)nsrc * 0.4f);    // fp32 mul + trunc = ref

        float*  ys  = (float*)s_pool;            // [N] = 8KB
        float4* ys4 = (float4*)ys;
        const float4* src4 = reinterpret_cast<const float4*>(g_y8 + b * N);
        __syncthreads();                          // protect reuse across tasks
        for (int l = tid; l < N / 4; l += 256)
            ys4[l] = src4[l];
        __syncthreads();

        int q  = tid & 7;                        // 8 threads per column
        int jj = tid >> 3;                       // 0..31
        int j  = jb + jj;
        float yj = ys[j];
        int cnt = 0;
#pragma unroll 4
        for (int l4 = q; l4 < N / 4; l4 += 8) {
            float4 v = ys4[l4];
            int l = l4 * 4;
            cnt += (l     < ns) && ((v.x > yj) || ((v.x == yj) && (l     < j)));
            cnt += (l + 1 < ns) && ((v.y > yj) || ((v.y == yj) && (l + 1 < j)));
            cnt += (l + 2 < ns) && ((v.z > yj) || ((v.z == yj) && (l + 2 < j)));
            cnt += (l + 3 < ns) && ((v.w > yj) || ((v.w == yj) && (l + 3 < j)));
        }
        cnt += __shfl_xor_sync(0xffffffffu, cnt, 1);
        cnt += __shfl_xor_sync(0xffffffffu, cnt, 2);
        cnt += __shfl_xor_sync(0xffffffffu, cnt, 4);

        if (q == 0) {
            bool act = (j < ns) && (cnt < kb) && (j < nsrc);
            float xj = g_x8[b * N + j];
            g_xm[b * N + j] = act ? xj : -1e30f;
            g_ym[b * N + j] = act ? yj : -1e30f;
        }
        if (blk == 0 && tid == 0)
            g_scale[b] = 1.0f / ((float)nsrc * 0.4f);
    }
    grid_barrier();

    // ─── Phase OUT: materialize output; 1024 tile-tasks of 16 rows ───────
    for (int t = bid; t < B * (N / TR); t += G) {
        int b    = t >> 7;                       // 128 tiles per batch
        int tile = t & 127;
        int row0 = b * N + tile * TR;

        const float4* y4  = reinterpret_cast<const float4*>(g_y8 + b * N);
        const float4* xm4 = reinterpret_cast<const float4*>(g_xm + b * N);
        int t0 = tid, t1 = tid + 256;
        float4 yA  = y4[t0],  yB  = y4[t1];
        float4 xmA = xm4[t0], xmB = xm4[t1];
        float sc = g_scale[b];

        float* s_x  = (float*)s_pool;            // [TR]
        float* s_ym = s_x + TR;                  // [TR]
        __syncthreads();                          // protect reuse across tasks
        if (tid < TR)
            s_x[tid] = g_x8[row0 + tid];
        else if (tid < 2 * TR)
            s_ym[tid - TR] = g_ym[row0 + tid - TR];
        __syncthreads();

#pragma unroll 4
        for (int rr = 0; rr < TR; rr++) {
            float xi  = s_x[rr];
            float ymi = s_ym[rr];
            float4* o4 = reinterpret_cast<float4*>(out + (size_t)(row0 + rr) * N);

            float4 rA, rB;
            {
                float e0 = xi + yA.x, e1 = xi + yA.y, e2 = xi + yA.z, e3 = xi + yA.w;
                rA.x = (fminf(e0, xmA.x + ymi) > 0.f) ? sc * tanh_fast(e0) : 0.f;
                rA.y = (fminf(e1, xmA.y + ymi) > 0.f) ? sc * tanh_fast(e1) : 0.f;
                rA.z = (fminf(e2, xmA.z + ymi) > 0.f) ? sc * tanh_fast(e2) : 0.f;
                rA.w = (fminf(e3, xmA.w + ymi) > 0.f) ? sc * tanh_fast(e3) : 0.f;
            }
            {
                float e0 = xi + yB.x, e1 = xi + yB.y, e2 = xi + yB.z, e3 = xi + yB.w;
                rB.x = (fminf(e0, xmB.x + ymi) > 0.f) ? sc * tanh_fast(e0) : 0.f;
                rB.y = (fminf(e1, xmB.y + ymi) > 0.f) ? sc * tanh_fast(e1) : 0.f;
                rB.z = (fminf(e2, xmB.z + ymi) > 0.f) ? sc * tanh_fast(e2) : 0.f;
                rB.w = (fminf(e3, xmB.w + ymi) > 0.f) ? sc * tanh_fast(e3) : 0.f;
            }
            __stcs(&o4[t0], rA);   // streaming store: output >> L2
            __stcs(&o4[t1], rB);
        }
    }
}

extern "C" void kernel_launch(void* const* d_in, const int* in_sizes, int n_in,
                              void* d_out, int out_size) {
    const float* emb1  = (const float*)d_in[0];
    const float* W     = (const float*)d_in[1];
    const float* a1    = (const float*)d_in[2];
    const float* a2    = (const float*)d_in[3];
    const int*   n_src = (const int*)d_in[4];
    const int*   nstgt = (const int*)d_in[5];
    float* out = (float*)d_out;

    // Exactly one co-resident wave (required by the software grid barrier).
    // Pure query APIs: legal under graph capture, no allocation.
    int dev = 0, sms = 0, maxb = 0;
    cudaGetDevice(&dev);
    cudaDeviceGetAttribute(&sms, cudaDevAttrMultiProcessorCount, dev);
    cudaOccupancyMaxActiveBlocksPerMultiprocessor(&maxb, k_persist, 256, 0);
    if (maxb < 1) maxb = 1;
    int grid = sms * maxb;
    if (grid > 2048) grid = 2048;   // never more blocks than largest task count

    k_persist<<<grid, 256>>>(emb1, W, a1, a2, n_src, nstgt, out);
}